// round 13
// baseline (speedup 1.0000x reference)
#include <cuda_runtime.h>
#include <cuda_fp16.h>

#define EPSV 1e-8f

constexpr int Bb = 64;
constexpr int N0 = 20000, E0 = 200000, M0 = 8000;
constexpr int E1 = 80000,  M1 = 2000;
constexpr int E2 = 20000,  M2 = 500;
constexpr int ETOT = E0 + E1 + E2;
constexpr int MTOT = M0 + M1 + M2;

constexpr int TB = N0 / 32;                    // 625 transpose blocks
constexpr int EB = (ETOT / 4 + 255) / 256;     // 293 edge blocks (4 edges/thread)

// ---- scratch (device globals; zero-initialized at module load) ----
__device__ float  g_xT[N0 * Bb];               // x transposed (node, batch) fp32
__device__ int    g_cnt[MTOT];                 // degree counters (re-zeroed by k_scan)
__device__ int    g_slot[ETOT];                // per-edge slot in its dst bucket
__device__ int    g_rp0[M0 + 1], g_rp1[M1 + 1], g_rp2[M2 + 1];
__device__ int    g_ce0[E0], g_ce1[E1], g_ce2[E2];
__device__ __half g_d1[M0 * Bb * 8];           // (node, batch, h) fp16
__device__ __half g_d2[M1 * Bb * 8];

// Blackwell packed fp32x2 add (sm_100a+)
__device__ __forceinline__ void padd(float2& a, const float2 b) {
    asm("add.rn.f32x2 %0, %0, %1;"
        : "+l"(reinterpret_cast<unsigned long long&>(a))
        : "l"(reinterpret_cast<const unsigned long long&>(b)));
}

// ================= K1: transpose (tiles) || histogram+slots || out init =============
__global__ void k_pre(const float* __restrict__ x,
                      const int* __restrict__ d0, const int* __restrict__ d1,
                      const int* __restrict__ d2,
                      const float* __restrict__ bout, float* __restrict__ out) {
    if (blockIdx.x == 0 && threadIdx.x < Bb) out[threadIdx.x] = bout[0];
    if (blockIdx.x < TB) {
        __shared__ float tile[64][33];
        int tid = threadIdx.x;
        int tx = tid & 31, ty = tid >> 5;
        int nb = blockIdx.x * 32;
#pragma unroll
        for (int i = 0; i < 64; i += 8)
            tile[ty + i][tx] = x[(ty + i) * N0 + nb + tx];
        __syncthreads();
        int r = tid >> 3, q = tid & 7;
        float4 a = make_float4(tile[q * 8 + 0][r], tile[q * 8 + 1][r],
                               tile[q * 8 + 2][r], tile[q * 8 + 3][r]);
        float4 b = make_float4(tile[q * 8 + 4][r], tile[q * 8 + 5][r],
                               tile[q * 8 + 6][r], tile[q * 8 + 7][r]);
        float4* dst = (float4*)&g_xT[(nb + r) * Bb + q * 8];
        dst[0] = a; dst[1] = b;
    } else {
        int i0 = ((blockIdx.x - TB) * 256 + threadIdx.x) * 4;
        if (i0 >= ETOT) return;
        const int* dp; int* cnt; int off;
        if (i0 < E0)            { dp = d0; cnt = g_cnt;            off = 0; }
        else if (i0 < E0 + E1)  { dp = d1; cnt = g_cnt + M0;       off = E0; }
        else                    { dp = d2; cnt = g_cnt + M0 + M1;  off = E0 + E1; }
        int4 dd = *(const int4*)&dp[i0 - off];
        int s0 = atomicAdd(&cnt[dd.x], 1);
        int s1 = atomicAdd(&cnt[dd.y], 1);
        int s2 = atomicAdd(&cnt[dd.z], 1);
        int s3 = atomicAdd(&cnt[dd.w], 1);
        *(int4*)&g_slot[i0] = make_int4(s0, s1, s2, s3);
    }
}

// ================= K2: exclusive scans (warp-shuffle, 8/thread); zero counters ======
__global__ void k_scan() {
    const int L = blockIdx.x;
    int* cnt    = (L == 0) ? g_cnt  : (L == 1) ? g_cnt + M0 : g_cnt + M0 + M1;
    int* rp     = (L == 0) ? g_rp0  : (L == 1) ? g_rp1      : g_rp2;
    const int m = (L == 0) ? M0     : (L == 1) ? M1         : M2;

    int t = threadIdx.x;
    int base = t * 8;
    int v[8];
    int s = 0;
#pragma unroll
    for (int k = 0; k < 8; k++) {
        int c = (base + k < m) ? cnt[base + k] : 0;
        s += c; v[k] = s;
    }
    int lane = t & 31, wid = t >> 5;
    int inc = s;
#pragma unroll
    for (int off = 1; off < 32; off <<= 1) {
        int n = __shfl_up_sync(0xffffffffu, inc, off);
        if (lane >= off) inc += n;
    }
    int wexcl = inc - s;
    __shared__ int wtot[32];
    if (lane == 31) wtot[wid] = inc;
    __syncthreads();
    if (t < 32) {
        int w = wtot[t];
        int wi = w;
#pragma unroll
        for (int off = 1; off < 32; off <<= 1) {
            int n = __shfl_up_sync(0xffffffffu, wi, off);
            if (t >= off) wi += n;
        }
        wtot[t] = wi - w;
    }
    __syncthreads();
    int off0 = wtot[wid] + wexcl;
#pragma unroll
    for (int k = 0; k < 8; k++)
        if (base + k < m) { rp[base + k + 1] = off0 + v[k]; cnt[base + k] = 0; }
    if (t == 0) rp[0] = 0;
}

// ================= K3: fill CSR via precomputed slots (no atomics) ==================
__global__ void k_fill(const int* __restrict__ s0, const int* __restrict__ d0,
                       const int* __restrict__ s1, const int* __restrict__ d1,
                       const int* __restrict__ s2, const int* __restrict__ d2) {
    int i0 = (blockIdx.x * 256 + threadIdx.x) * 4;
    if (i0 >= ETOT) return;
    const int *sp, *dp, *rp; int* ce; int off;
    if (i0 < E0)            { sp = s0; dp = d0; rp = g_rp0; ce = g_ce0; off = 0; }
    else if (i0 < E0 + E1)  { sp = s1; dp = d1; rp = g_rp1; ce = g_ce1; off = E0; }
    else                    { sp = s2; dp = d2; rp = g_rp2; ce = g_ce2; off = E0 + E1; }
    int j = i0 - off;
    int4 ss = *(const int4*)&sp[j];
    int4 dd = *(const int4*)&dp[j];
    int4 sl = *(const int4*)&g_slot[i0];
    ce[rp[dd.x] + sl.x] = ss.x;
    ce[rp[dd.y] + sl.y] = ss.y;
    ce[rp[dd.z] + sl.z] = ss.z;
    ce[rp[dd.w] + sl.w] = ss.w;
}

// ===== K4: layer 0 — warp per node; lane = (edge-quad el, batch-octet oct), fp32 ====
__global__ void k_agg0(const float* __restrict__ W0) {
    const int lane = threadIdx.x & 31;
    const int el   = lane >> 3;            // edge slot within quad: 0..3
    const int oct  = lane & 7;             // batch octet: 0..7
    const int node = blockIdx.x * 8 + (threadIdx.x >> 5);
    float w0r[8];
#pragma unroll
    for (int h = 0; h < 8; h++) w0r[h] = W0[h];

    int beg = g_rp0[node], end = g_rp0[node + 1];
    float2 acc[4];
#pragma unroll
    for (int j = 0; j < 4; j++) acc[j] = make_float2(0.f, 0.f);
    for (int c = beg; c < end; c += 32) {
        int nchunk = min(32, end - c);
        int idx = (c + lane < end) ? g_ce0[c + lane] : 0;
        int nr = nchunk >> 2;
#pragma unroll 2
        for (int r = 0; r < nr; r++) {
            int src = __shfl_sync(0xffffffffu, idx, r * 4 + el);
            const float4* p = (const float4*)&g_xT[src * Bb + oct * 8];
            float4 va = p[0], vb = p[1];
            padd(acc[0], make_float2(va.x, va.y));
            padd(acc[1], make_float2(va.z, va.w));
            padd(acc[2], make_float2(vb.x, vb.y));
            padd(acc[3], make_float2(vb.z, vb.w));
        }
        int rem = nchunk & 3;
        if (rem) {
            int src = __shfl_sync(0xffffffffu, idx, nr * 4 + min(el, rem - 1));
            if (el < rem) {
                const float4* p = (const float4*)&g_xT[src * Bb + oct * 8];
                float4 va = p[0], vb = p[1];
                padd(acc[0], make_float2(va.x, va.y));
                padd(acc[1], make_float2(va.z, va.w));
                padd(acc[2], make_float2(vb.x, vb.y));
                padd(acc[3], make_float2(vb.z, vb.w));
            }
        }
    }
    float s[8];
    s[0] = acc[0].x; s[1] = acc[0].y; s[2] = acc[1].x; s[3] = acc[1].y;
    s[4] = acc[2].x; s[5] = acc[2].y; s[6] = acc[3].x; s[7] = acc[3].y;
    // reduce across the 4 edge-slots (lane bits 3,4)
#pragma unroll
    for (int off = 8; off <= 16; off <<= 1) {
#pragma unroll
        for (int j = 0; j < 8; j++)
            s[j] += __shfl_xor_sync(0xffffffffu, s[j], off);
    }
    float inv = 1.f / fmaxf((float)(end - beg), 1.f);
#pragma unroll
    for (int j = 0; j < 8; j++) s[j] *= inv;
    float mn = s[0], mx = s[0];
#pragma unroll
    for (int j = 1; j < 8; j++) { mn = fminf(mn, s[j]); mx = fmaxf(mx, s[j]); }
#pragma unroll
    for (int off = 1; off <= 4; off <<= 1) {
        mn = fminf(mn, __shfl_xor_sync(0xffffffffu, mn, off));
        mx = fmaxf(mx, __shfl_xor_sync(0xffffffffu, mx, off));
    }
    // each lane writes 2 batches: oct*8 + el*2 (+1)
    float v0 = s[el * 2], v1 = s[el * 2 + 1];
    __half2 o0[4], o1[4];
#pragma unroll
    for (int h = 0; h < 4; h++) {
        float wa = w0r[2 * h], wb = w0r[2 * h + 1];
        float loa = (wa >= 0.f) ? wa * mn : wa * mx;
        float hia = (wa >= 0.f) ? wa * mx : wa * mn;
        float lob = (wb >= 0.f) ? wb * mn : wb * mx;
        float hib = (wb >= 0.f) ? wb * mx : wb * mn;
        float ia = 1.f / (hia - loa + EPSV), ib = 1.f / (hib - lob + EPSV);
        o0[h] = __floats2half2_rn(fmaxf((wa * v0 - loa) * ia, 0.f),
                                  fmaxf((wb * v0 - lob) * ib, 0.f));
        o1[h] = __floats2half2_rn(fmaxf((wa * v1 - loa) * ia, 0.f),
                                  fmaxf((wb * v1 - lob) * ib, 0.f));
    }
    int bA = oct * 8 + el * 2;
    *(uint4*)&g_d1[(node * Bb + bA) * 8]     = *(uint4*)o0;
    *(uint4*)&g_d1[(node * Bb + bA + 1) * 8] = *(uint4*)o1;
}

// ===== K5: layer 1 — 128 thr/node (2 edge-chunks x 64 batches), 2 nodes/CTA =========
__global__ void k_agg1(const float* __restrict__ W1) {
    __shared__ float s_W[64];
    __shared__ float s_part[2][64][8];
    __shared__ float s_mn[2][2][8], s_mx[2][2][8];
    const int tid = threadIdx.x;
    if (tid < 64) s_W[tid] = W1[tid];
    __syncthreads();
    const int half  = tid >> 7;            // node within CTA: 0/1
    const int chunk = (tid >> 6) & 1;      // edge chunk: 0/1
    const int b     = tid & 63;
    const int node  = blockIdx.x * 2 + half;
    int beg = g_rp1[node], end = g_rp1[node + 1];
    float2 acc2[4];
#pragma unroll
    for (int h = 0; h < 4; h++) acc2[h] = make_float2(0.f, 0.f);
    int j = beg + chunk;
    for (; j + 2 < end; j += 4) {          // 2 independent loads / iter
        int iA = g_ce1[j], iB = g_ce1[j + 2];
        uint4 rA = *(const uint4*)&g_d1[(iA * Bb + b) * 8];
        uint4 rB = *(const uint4*)&g_d1[(iB * Bb + b) * 8];
        padd(acc2[0], __half22float2(*(__half2*)&rA.x));
        padd(acc2[1], __half22float2(*(__half2*)&rA.y));
        padd(acc2[2], __half22float2(*(__half2*)&rA.z));
        padd(acc2[3], __half22float2(*(__half2*)&rA.w));
        padd(acc2[0], __half22float2(*(__half2*)&rB.x));
        padd(acc2[1], __half22float2(*(__half2*)&rB.y));
        padd(acc2[2], __half22float2(*(__half2*)&rB.z));
        padd(acc2[3], __half22float2(*(__half2*)&rB.w));
    }
    if (j < end) {
        int iA = g_ce1[j];
        uint4 rA = *(const uint4*)&g_d1[(iA * Bb + b) * 8];
        padd(acc2[0], __half22float2(*(__half2*)&rA.x));
        padd(acc2[1], __half22float2(*(__half2*)&rA.y));
        padd(acc2[2], __half22float2(*(__half2*)&rA.z));
        padd(acc2[3], __half22float2(*(__half2*)&rA.w));
    }
    if (chunk == 1) {
#pragma unroll
        for (int h = 0; h < 4; h++) {
            s_part[half][b][2 * h]     = acc2[h].x;
            s_part[half][b][2 * h + 1] = acc2[h].y;
        }
    }
    __syncthreads();
    float t[8];
    if (chunk == 0) {
        const int lane = tid & 31;
        const int wig  = (tid >> 5) & 1;
        float acc[8];
        acc[0] = acc2[0].x; acc[1] = acc2[0].y; acc[2] = acc2[1].x; acc[3] = acc2[1].y;
        acc[4] = acc2[2].x; acc[5] = acc2[2].y; acc[6] = acc2[3].x; acc[7] = acc2[3].y;
#pragma unroll
        for (int h = 0; h < 8; h++) acc[h] += s_part[half][b][h];
        float inv = 1.f / fmaxf((float)(end - beg), 1.f);
        float mn[8], mx[8];
#pragma unroll
        for (int h = 0; h < 8; h++) {
            float v = 0.f;
#pragma unroll
            for (int d = 0; d < 8; d++) v += s_W[h * 8 + d] * acc[d];
            t[h] = v * inv;
            mn[h] = t[h]; mx[h] = t[h];
        }
#pragma unroll
        for (int off = 16; off; off >>= 1) {
#pragma unroll
            for (int h = 0; h < 8; h++) {
                mn[h] = fminf(mn[h], __shfl_xor_sync(0xffffffffu, mn[h], off));
                mx[h] = fmaxf(mx[h], __shfl_xor_sync(0xffffffffu, mx[h], off));
            }
        }
        if (lane == 0) {
#pragma unroll
            for (int h = 0; h < 8; h++) { s_mn[half][wig][h] = mn[h]; s_mx[half][wig][h] = mx[h]; }
        }
    }
    __syncthreads();                       // CTA-uniform
    if (chunk == 0) {
        __half2 p[4];
#pragma unroll
        for (int h = 0; h < 4; h++) {
            float lo0 = fminf(s_mn[half][0][2 * h],     s_mn[half][1][2 * h]);
            float hi0 = fmaxf(s_mx[half][0][2 * h],     s_mx[half][1][2 * h]);
            float lo1 = fminf(s_mn[half][0][2 * h + 1], s_mn[half][1][2 * h + 1]);
            float hi1 = fmaxf(s_mx[half][0][2 * h + 1], s_mx[half][1][2 * h + 1]);
            p[h] = __floats2half2_rn(fmaxf((t[2 * h]     - lo0) / (hi0 - lo0 + EPSV), 0.f),
                                     fmaxf((t[2 * h + 1] - lo1) / (hi1 - lo1 + EPSV), 0.f));
        }
        *(uint4*)&g_d2[(node * Bb + b) * 8] = *(uint4*)p;
    }
}

// ===== K6: layer 2 + out — 512 thr/node (8 edge-chunks x 64 batches), grid M2 =======
__global__ void k_agg2out(const float* __restrict__ W2, const float* __restrict__ Wout,
                          float* __restrict__ out) {
    __shared__ float s_W[64];
    __shared__ float s_acc[8][64][8];
    __shared__ float s_mn[2][8], s_mx[2][8];
    const int tid   = threadIdx.x;
    const int chunk = tid >> 6;            // 0..7
    const int b     = tid & 63;
    const int node  = blockIdx.x;
    if (tid < 64) s_W[tid] = W2[tid];
    __syncthreads();
    int beg = g_rp2[node], end = g_rp2[node + 1];
    float2 acc2[4];
#pragma unroll
    for (int h = 0; h < 4; h++) acc2[h] = make_float2(0.f, 0.f);
    for (int j = beg + chunk; j < end; j += 8) {
        int src = g_ce2[j];
        uint4 r = *(const uint4*)&g_d2[(src * Bb + b) * 8];
        padd(acc2[0], __half22float2(*(__half2*)&r.x));
        padd(acc2[1], __half22float2(*(__half2*)&r.y));
        padd(acc2[2], __half22float2(*(__half2*)&r.z));
        padd(acc2[3], __half22float2(*(__half2*)&r.w));
    }
#pragma unroll
    for (int h = 0; h < 4; h++) {
        s_acc[chunk][b][2 * h]     = acc2[h].x;
        s_acc[chunk][b][2 * h + 1] = acc2[h].y;
    }
    __syncthreads();
    float t[8];
    if (tid < 64) {
        const int lane = tid & 31;
        const int wig  = tid >> 5;
        float acc[8], mn[8], mx[8];
#pragma unroll
        for (int h = 0; h < 8; h++) {
            float v = 0.f;
#pragma unroll
            for (int c = 0; c < 8; c++) v += s_acc[c][b][h];
            acc[h] = v;
        }
        float inv = 1.f / fmaxf((float)(end - beg), 1.f);
#pragma unroll
        for (int h = 0; h < 8; h++) {
            float v = 0.f;
#pragma unroll
            for (int d = 0; d < 8; d++) v += s_W[h * 8 + d] * acc[d];
            t[h] = v * inv;
            mn[h] = t[h]; mx[h] = t[h];
        }
#pragma unroll
        for (int off = 16; off; off >>= 1) {
#pragma unroll
            for (int h = 0; h < 8; h++) {
                mn[h] = fminf(mn[h], __shfl_xor_sync(0xffffffffu, mn[h], off));
                mx[h] = fmaxf(mx[h], __shfl_xor_sync(0xffffffffu, mx[h], off));
            }
        }
        if (lane == 0) {
#pragma unroll
            for (int h = 0; h < 8; h++) { s_mn[wig][h] = mn[h]; s_mx[wig][h] = mx[h]; }
        }
    }
    __syncthreads();                       // CTA-uniform
    if (tid < 64) {
        float p = 0.f;
#pragma unroll
        for (int h = 0; h < 8; h++) {
            float lo = fminf(s_mn[0][h], s_mn[1][h]);
            float hi = fmaxf(s_mx[0][h], s_mx[1][h]);
            float o = fmaxf((t[h] - lo) / (hi - lo + EPSV), 0.f);
            p += o * Wout[node * 8 + h];
        }
        atomicAdd(&out[b], p);
    }
}

extern "C" void kernel_launch(void* const* d_in, const int* in_sizes, int n_in,
                              void* d_out, int out_size) {
    const float* x    = (const float*)d_in[0];
    const int*   e0s  = (const int*)d_in[1];
    const int*   e0d  = (const int*)d_in[2];
    const int*   e1s  = (const int*)d_in[3];
    const int*   e1d  = (const int*)d_in[4];
    const int*   e2s  = (const int*)d_in[5];
    const int*   e2d  = (const int*)d_in[6];
    const float* W0   = (const float*)d_in[7];
    const float* W1   = (const float*)d_in[8];
    const float* W2   = (const float*)d_in[9];
    const float* Wout = (const float*)d_in[10];
    const float* bout = (const float*)d_in[11];
    float* out = (float*)d_out;

    k_pre<<<TB + EB, 256>>>(x, e0d, e1d, e2d, bout, out);
    k_scan<<<3, 1024>>>();
    k_fill<<<EB, 256>>>(e0s, e0d, e1s, e1d, e2s, e2d);
    k_agg0<<<M0 / 8, 256>>>(W0);
    k_agg1<<<M1 / 2, 256>>>(W1);
    k_agg2out<<<M2, 512>>>(W2, Wout, out);
}

// round 14
// speedup vs baseline: 1.0824x; 1.0824x over previous
#include <cuda_runtime.h>
#include <cuda_fp16.h>

#define EPSV 1e-8f

constexpr int Bb = 64;
constexpr int N0 = 20000, E0 = 200000, M0 = 8000;
constexpr int E1 = 80000,  M1 = 2000;
constexpr int E2 = 20000,  M2 = 500;
constexpr int ETOT = E0 + E1 + E2;
constexpr int MTOT = M0 + M1 + M2;

constexpr int TB = N0 / 32;                    // 625 transpose blocks
constexpr int EB = (ETOT / 4 + 255) / 256;     // 293 edge blocks (4 edges/thread)

// ---- scratch (device globals; zero-initialized at module load) ----
__device__ __half g_xT[N0 * Bb];               // x transposed (node, batch) fp16
__device__ int    g_cnt[MTOT];                 // degree counters (re-zeroed by k_scan)
__device__ int    g_slot[ETOT];                // per-edge slot in its dst bucket
__device__ int    g_rp0[M0 + 1], g_rp1[M1 + 1], g_rp2[M2 + 1];
__device__ int    g_ce0[E0], g_ce1[E1], g_ce2[E2];
__device__ __half g_d1[M0 * Bb * 8];           // (node, batch, h) fp16
__device__ __half g_d2[M1 * Bb * 8];

// ================= K1: transpose (tiles) || histogram+slots || out init =============
__global__ void k_pre(const float* __restrict__ x,
                      const int* __restrict__ d0, const int* __restrict__ d1,
                      const int* __restrict__ d2,
                      const float* __restrict__ bout, float* __restrict__ out) {
    if (blockIdx.x == 0 && threadIdx.x < Bb) out[threadIdx.x] = bout[0];
    if (blockIdx.x < TB) {
        __shared__ float tile[64][33];
        int tid = threadIdx.x;
        int tx = tid & 31, ty = tid >> 5;
        int nb = blockIdx.x * 32;
#pragma unroll
        for (int i = 0; i < 64; i += 8)
            tile[ty + i][tx] = x[(ty + i) * N0 + nb + tx];
        __syncthreads();
        int r = tid >> 3, q = tid & 7;
        __half2 h[4];
#pragma unroll
        for (int k = 0; k < 4; k++)
            h[k] = __floats2half2_rn(tile[q * 8 + 2 * k][r], tile[q * 8 + 2 * k + 1][r]);
        *(uint4*)&g_xT[(nb + r) * Bb + q * 8] = *(uint4*)h;
    } else {
        int i0 = ((blockIdx.x - TB) * 256 + threadIdx.x) * 4;
        if (i0 >= ETOT) return;
        const int* dp; int* cnt; int off;
        if (i0 < E0)            { dp = d0; cnt = g_cnt;            off = 0; }
        else if (i0 < E0 + E1)  { dp = d1; cnt = g_cnt + M0;       off = E0; }
        else                    { dp = d2; cnt = g_cnt + M0 + M1;  off = E0 + E1; }
        int4 dd = *(const int4*)&dp[i0 - off];
        int s0 = atomicAdd(&cnt[dd.x], 1);
        int s1 = atomicAdd(&cnt[dd.y], 1);
        int s2 = atomicAdd(&cnt[dd.z], 1);
        int s3 = atomicAdd(&cnt[dd.w], 1);
        *(int4*)&g_slot[i0] = make_int4(s0, s1, s2, s3);
    }
}

// ================= K2: exclusive scans (warp-shuffle, 8/thread); zero counters ======
__global__ void k_scan() {
    const int L = blockIdx.x;
    int* cnt    = (L == 0) ? g_cnt  : (L == 1) ? g_cnt + M0 : g_cnt + M0 + M1;
    int* rp     = (L == 0) ? g_rp0  : (L == 1) ? g_rp1      : g_rp2;
    const int m = (L == 0) ? M0     : (L == 1) ? M1         : M2;

    int t = threadIdx.x;
    int base = t * 8;
    int v[8];
    int s = 0;
#pragma unroll
    for (int k = 0; k < 8; k++) {
        int c = (base + k < m) ? cnt[base + k] : 0;
        s += c; v[k] = s;
    }
    int lane = t & 31, wid = t >> 5;
    int inc = s;
#pragma unroll
    for (int off = 1; off < 32; off <<= 1) {
        int n = __shfl_up_sync(0xffffffffu, inc, off);
        if (lane >= off) inc += n;
    }
    int wexcl = inc - s;
    __shared__ int wtot[32];
    if (lane == 31) wtot[wid] = inc;
    __syncthreads();
    if (t < 32) {
        int w = wtot[t];
        int wi = w;
#pragma unroll
        for (int off = 1; off < 32; off <<= 1) {
            int n = __shfl_up_sync(0xffffffffu, wi, off);
            if (t >= off) wi += n;
        }
        wtot[t] = wi - w;
    }
    __syncthreads();
    int off0 = wtot[wid] + wexcl;
#pragma unroll
    for (int k = 0; k < 8; k++)
        if (base + k < m) { rp[base + k + 1] = off0 + v[k]; cnt[base + k] = 0; }
    if (t == 0) rp[0] = 0;
}

// ================= K3: fill CSR via precomputed slots (no atomics) ==================
__global__ void k_fill(const int* __restrict__ s0, const int* __restrict__ d0,
                       const int* __restrict__ s1, const int* __restrict__ d1,
                       const int* __restrict__ s2, const int* __restrict__ d2) {
    int i0 = (blockIdx.x * 256 + threadIdx.x) * 4;
    if (i0 >= ETOT) return;
    const int *sp, *dp, *rp; int* ce; int off;
    if (i0 < E0)            { sp = s0; dp = d0; rp = g_rp0; ce = g_ce0; off = 0; }
    else if (i0 < E0 + E1)  { sp = s1; dp = d1; rp = g_rp1; ce = g_ce1; off = E0; }
    else                    { sp = s2; dp = d2; rp = g_rp2; ce = g_ce2; off = E0 + E1; }
    int j = i0 - off;
    int4 ss = *(const int4*)&sp[j];
    int4 dd = *(const int4*)&dp[j];
    int4 sl = *(const int4*)&g_slot[i0];
    ce[rp[dd.x] + sl.x] = ss.x;
    ce[rp[dd.y] + sl.y] = ss.y;
    ce[rp[dd.z] + sl.z] = ss.z;
    ce[rp[dd.w] + sl.w] = ss.w;
}

// ===== K4: layer 0 — warp per node; lane = (edge-quad el, batch-octet oct), fp16 ====
__global__ void k_agg0(const float* __restrict__ W0) {
    const int lane = threadIdx.x & 31;
    const int el   = lane >> 3;            // edge slot within quad: 0..3
    const int oct  = lane & 7;             // batch octet: 0..7
    const int node = blockIdx.x * 8 + (threadIdx.x >> 5);
    float w0r[8];
#pragma unroll
    for (int h = 0; h < 8; h++) w0r[h] = W0[h];

    int beg = g_rp0[node], end = g_rp0[node + 1];
    float acc[8];
#pragma unroll
    for (int j = 0; j < 8; j++) acc[j] = 0.f;
    for (int c = beg; c < end; c += 32) {
        int nchunk = min(32, end - c);
        int idx = (c + lane < end) ? g_ce0[c + lane] : 0;
        int nr = nchunk >> 2;
#pragma unroll 4
        for (int r = 0; r < nr; r++) {
            int src = __shfl_sync(0xffffffffu, idx, r * 4 + el);
            uint4 v = *(const uint4*)&g_xT[src * Bb + oct * 8];
            float2 f;
            f = __half22float2(*(__half2*)&v.x); acc[0] += f.x; acc[1] += f.y;
            f = __half22float2(*(__half2*)&v.y); acc[2] += f.x; acc[3] += f.y;
            f = __half22float2(*(__half2*)&v.z); acc[4] += f.x; acc[5] += f.y;
            f = __half22float2(*(__half2*)&v.w); acc[6] += f.x; acc[7] += f.y;
        }
        int rem = nchunk & 3;
        if (rem) {
            int src = __shfl_sync(0xffffffffu, idx, nr * 4 + min(el, rem - 1));
            if (el < rem) {
                uint4 v = *(const uint4*)&g_xT[src * Bb + oct * 8];
                float2 f;
                f = __half22float2(*(__half2*)&v.x); acc[0] += f.x; acc[1] += f.y;
                f = __half22float2(*(__half2*)&v.y); acc[2] += f.x; acc[3] += f.y;
                f = __half22float2(*(__half2*)&v.z); acc[4] += f.x; acc[5] += f.y;
                f = __half22float2(*(__half2*)&v.w); acc[6] += f.x; acc[7] += f.y;
            }
        }
    }
    // reduce across the 4 edge-slots (lane bits 3,4)
#pragma unroll
    for (int off = 8; off <= 16; off <<= 1) {
#pragma unroll
        for (int j = 0; j < 8; j++)
            acc[j] += __shfl_xor_sync(0xffffffffu, acc[j], off);
    }
    float inv = 1.f / fmaxf((float)(end - beg), 1.f);
    float s[8];
#pragma unroll
    for (int j = 0; j < 8; j++) s[j] = acc[j] * inv;
    float mn = s[0], mx = s[0];
#pragma unroll
    for (int j = 1; j < 8; j++) { mn = fminf(mn, s[j]); mx = fmaxf(mx, s[j]); }
#pragma unroll
    for (int off = 1; off <= 4; off <<= 1) {
        mn = fminf(mn, __shfl_xor_sync(0xffffffffu, mn, off));
        mx = fmaxf(mx, __shfl_xor_sync(0xffffffffu, mx, off));
    }
    // each lane writes 2 batches: oct*8 + el*2 (+1)
    float v0 = s[el * 2], v1 = s[el * 2 + 1];
    __half2 o0[4], o1[4];
#pragma unroll
    for (int h = 0; h < 4; h++) {
        float wa = w0r[2 * h], wb = w0r[2 * h + 1];
        float loa = (wa >= 0.f) ? wa * mn : wa * mx;
        float hia = (wa >= 0.f) ? wa * mx : wa * mn;
        float lob = (wb >= 0.f) ? wb * mn : wb * mx;
        float hib = (wb >= 0.f) ? wb * mx : wb * mn;
        float ia = 1.f / (hia - loa + EPSV), ib = 1.f / (hib - lob + EPSV);
        o0[h] = __floats2half2_rn(fmaxf((wa * v0 - loa) * ia, 0.f),
                                  fmaxf((wb * v0 - lob) * ib, 0.f));
        o1[h] = __floats2half2_rn(fmaxf((wa * v1 - loa) * ia, 0.f),
                                  fmaxf((wb * v1 - lob) * ib, 0.f));
    }
    int bA = oct * 8 + el * 2;
    *(uint4*)&g_d1[(node * Bb + bA) * 8]     = *(uint4*)o0;
    *(uint4*)&g_d1[(node * Bb + bA + 1) * 8] = *(uint4*)o1;
}

// ===== K5: layer 1 — 128 thr/node (2 edge-chunks x 64 batches), 2 nodes/CTA =========
__global__ void k_agg1(const float* __restrict__ W1) {
    __shared__ float s_W[64];
    __shared__ float s_part[2][64][8];
    __shared__ float s_mn[2][2][8], s_mx[2][2][8];
    const int tid = threadIdx.x;
    if (tid < 64) s_W[tid] = W1[tid];
    __syncthreads();
    const int half  = tid >> 7;            // node within CTA: 0/1
    const int chunk = (tid >> 6) & 1;      // edge chunk: 0/1
    const int b     = tid & 63;
    const int node  = blockIdx.x * 2 + half;
    int beg = g_rp1[node], end = g_rp1[node + 1];
    float acc[8];
#pragma unroll
    for (int h = 0; h < 8; h++) acc[h] = 0.f;
    int j = beg + chunk;
    for (; j + 2 < end; j += 4) {          // 2 independent loads / iter
        int iA = g_ce1[j], iB = g_ce1[j + 2];
        uint4 rA = *(const uint4*)&g_d1[(iA * Bb + b) * 8];
        uint4 rB = *(const uint4*)&g_d1[(iB * Bb + b) * 8];
        float2 f;
        f = __half22float2(*(__half2*)&rA.x); acc[0] += f.x; acc[1] += f.y;
        f = __half22float2(*(__half2*)&rA.y); acc[2] += f.x; acc[3] += f.y;
        f = __half22float2(*(__half2*)&rA.z); acc[4] += f.x; acc[5] += f.y;
        f = __half22float2(*(__half2*)&rA.w); acc[6] += f.x; acc[7] += f.y;
        f = __half22float2(*(__half2*)&rB.x); acc[0] += f.x; acc[1] += f.y;
        f = __half22float2(*(__half2*)&rB.y); acc[2] += f.x; acc[3] += f.y;
        f = __half22float2(*(__half2*)&rB.z); acc[4] += f.x; acc[5] += f.y;
        f = __half22float2(*(__half2*)&rB.w); acc[6] += f.x; acc[7] += f.y;
    }
    if (j < end) {
        int iA = g_ce1[j];
        uint4 rA = *(const uint4*)&g_d1[(iA * Bb + b) * 8];
        float2 f;
        f = __half22float2(*(__half2*)&rA.x); acc[0] += f.x; acc[1] += f.y;
        f = __half22float2(*(__half2*)&rA.y); acc[2] += f.x; acc[3] += f.y;
        f = __half22float2(*(__half2*)&rA.z); acc[4] += f.x; acc[5] += f.y;
        f = __half22float2(*(__half2*)&rA.w); acc[6] += f.x; acc[7] += f.y;
    }
    if (chunk == 1) {
#pragma unroll
        for (int h = 0; h < 8; h++) s_part[half][b][h] = acc[h];
    }
    __syncthreads();
    float t[8];
    if (chunk == 0) {
        const int lane = tid & 31;
        const int wig  = (tid >> 5) & 1;
#pragma unroll
        for (int h = 0; h < 8; h++) acc[h] += s_part[half][b][h];
        float inv = 1.f / fmaxf((float)(end - beg), 1.f);
        float mn[8], mx[8];
#pragma unroll
        for (int h = 0; h < 8; h++) {
            float v = 0.f;
#pragma unroll
            for (int d = 0; d < 8; d++) v += s_W[h * 8 + d] * acc[d];
            t[h] = v * inv;
            mn[h] = t[h]; mx[h] = t[h];
        }
#pragma unroll
        for (int off = 16; off; off >>= 1) {
#pragma unroll
            for (int h = 0; h < 8; h++) {
                mn[h] = fminf(mn[h], __shfl_xor_sync(0xffffffffu, mn[h], off));
                mx[h] = fmaxf(mx[h], __shfl_xor_sync(0xffffffffu, mx[h], off));
            }
        }
        if (lane == 0) {
#pragma unroll
            for (int h = 0; h < 8; h++) { s_mn[half][wig][h] = mn[h]; s_mx[half][wig][h] = mx[h]; }
        }
    }
    __syncthreads();                       // CTA-uniform
    if (chunk == 0) {
        __half2 p[4];
#pragma unroll
        for (int h = 0; h < 4; h++) {
            float lo0 = fminf(s_mn[half][0][2 * h],     s_mn[half][1][2 * h]);
            float hi0 = fmaxf(s_mx[half][0][2 * h],     s_mx[half][1][2 * h]);
            float lo1 = fminf(s_mn[half][0][2 * h + 1], s_mn[half][1][2 * h + 1]);
            float hi1 = fmaxf(s_mx[half][0][2 * h + 1], s_mx[half][1][2 * h + 1]);
            p[h] = __floats2half2_rn(fmaxf((t[2 * h]     - lo0) / (hi0 - lo0 + EPSV), 0.f),
                                     fmaxf((t[2 * h + 1] - lo1) / (hi1 - lo1 + EPSV), 0.f));
        }
        *(uint4*)&g_d2[(node * Bb + b) * 8] = *(uint4*)p;
    }
}

// ===== K6: layer 2 + out — 512 thr/node (8 edge-chunks x 64 batches), grid M2 =======
__global__ void k_agg2out(const float* __restrict__ W2, const float* __restrict__ Wout,
                          float* __restrict__ out) {
    __shared__ float s_W[64];
    __shared__ float s_acc[8][64][8];
    __shared__ float s_mn[2][8], s_mx[2][8];
    const int tid   = threadIdx.x;
    const int chunk = tid >> 6;            // 0..7
    const int b     = tid & 63;
    const int node  = blockIdx.x;
    if (tid < 64) s_W[tid] = W2[tid];
    __syncthreads();
    int beg = g_rp2[node], end = g_rp2[node + 1];
    float acc[8];
#pragma unroll
    for (int h = 0; h < 8; h++) acc[h] = 0.f;
    for (int j = beg + chunk; j < end; j += 8) {
        int src = g_ce2[j];
        uint4 r = *(const uint4*)&g_d2[(src * Bb + b) * 8];
        float2 f;
        f = __half22float2(*(__half2*)&r.x); acc[0] += f.x; acc[1] += f.y;
        f = __half22float2(*(__half2*)&r.y); acc[2] += f.x; acc[3] += f.y;
        f = __half22float2(*(__half2*)&r.z); acc[4] += f.x; acc[5] += f.y;
        f = __half22float2(*(__half2*)&r.w); acc[6] += f.x; acc[7] += f.y;
    }
#pragma unroll
    for (int h = 0; h < 8; h++) s_acc[chunk][b][h] = acc[h];
    __syncthreads();
    float t[8];
    if (tid < 64) {
        const int lane = tid & 31;
        const int wig  = tid >> 5;
        float mn[8], mx[8];
#pragma unroll
        for (int h = 0; h < 8; h++) {
            float v = 0.f;
#pragma unroll
            for (int c = 0; c < 8; c++) v += s_acc[c][b][h];
            acc[h] = v;
        }
        float inv = 1.f / fmaxf((float)(end - beg), 1.f);
#pragma unroll
        for (int h = 0; h < 8; h++) {
            float v = 0.f;
#pragma unroll
            for (int d = 0; d < 8; d++) v += s_W[h * 8 + d] * acc[d];
            t[h] = v * inv;
            mn[h] = t[h]; mx[h] = t[h];
        }
#pragma unroll
        for (int off = 16; off; off >>= 1) {
#pragma unroll
            for (int h = 0; h < 8; h++) {
                mn[h] = fminf(mn[h], __shfl_xor_sync(0xffffffffu, mn[h], off));
                mx[h] = fmaxf(mx[h], __shfl_xor_sync(0xffffffffu, mx[h], off));
            }
        }
        if (lane == 0) {
#pragma unroll
            for (int h = 0; h < 8; h++) { s_mn[wig][h] = mn[h]; s_mx[wig][h] = mx[h]; }
        }
    }
    __syncthreads();                       // CTA-uniform
    if (tid < 64) {
        float p = 0.f;
#pragma unroll
        for (int h = 0; h < 8; h++) {
            float lo = fminf(s_mn[0][h], s_mn[1][h]);
            float hi = fmaxf(s_mx[0][h], s_mx[1][h]);
            float o = fmaxf((t[h] - lo) / (hi - lo + EPSV), 0.f);
            p += o * Wout[node * 8 + h];
        }
        atomicAdd(&out[b], p);
    }
}

extern "C" void kernel_launch(void* const* d_in, const int* in_sizes, int n_in,
                              void* d_out, int out_size) {
    const float* x    = (const float*)d_in[0];
    const int*   e0s  = (const int*)d_in[1];
    const int*   e0d  = (const int*)d_in[2];
    const int*   e1s  = (const int*)d_in[3];
    const int*   e1d  = (const int*)d_in[4];
    const int*   e2s  = (const int*)d_in[5];
    const int*   e2d  = (const int*)d_in[6];
    const float* W0   = (const float*)d_in[7];
    const float* W1   = (const float*)d_in[8];
    const float* W2   = (const float*)d_in[9];
    const float* Wout = (const float*)d_in[10];
    const float* bout = (const float*)d_in[11];
    float* out = (float*)d_out;

    k_pre<<<TB + EB, 256>>>(x, e0d, e1d, e2d, bout, out);
    k_scan<<<3, 1024>>>();
    k_fill<<<EB, 256>>>(e0s, e0d, e1s, e1d, e2s, e2d);
    k_agg0<<<M0 / 8, 256>>>(W0);
    k_agg1<<<M1 / 2, 256>>>(W1);
    k_agg2out<<<M2, 512>>>(W2, Wout, out);
}

// round 15
// speedup vs baseline: 1.4691x; 1.3573x over previous
#include <cuda_runtime.h>
#include <cuda_fp16.h>

#define EPSV 1e-8f

constexpr int Bb = 64;
constexpr int N0 = 20000, E0 = 200000, M0 = 8000;
constexpr int E1 = 80000,  M1 = 2000;
constexpr int E2 = 20000,  M2 = 500;
constexpr int ETOT = E0 + E1 + E2;
constexpr int MTOT = M0 + M1 + M2;

constexpr int TB = N0 / 32;                    // 625 transpose blocks
constexpr int EB = (ETOT / 4 + 255) / 256;     // 293 edge blocks (4 edges/thread)

// ---- scratch (device globals; zero-initialized at module load) ----
__device__ __half g_xT[N0 * Bb];               // x transposed (node, batch) fp16
__device__ int    g_cnt[MTOT];                 // degree counters (re-zeroed by k_scan)
__device__ int    g_slot[ETOT];                // per-edge slot in its dst bucket
__device__ int    g_rp0[M0 + 1], g_rp1[M1 + 1], g_rp2[M2 + 1];
__device__ int    g_ce0[E0], g_ce1[E1], g_ce2[E2];
__device__ float  g_u1[M0 * Bb];               // layer-0 scalar minmax output, fp32
__device__ float  g_u2[M1 * Bb];               // layer-1 scalar minmax output, fp32

// ================= K1: transpose (tiles) || histogram+slots || out init =============
__global__ void k_pre(const float* __restrict__ x,
                      const int* __restrict__ d0, const int* __restrict__ d1,
                      const int* __restrict__ d2,
                      const float* __restrict__ bout, float* __restrict__ out) {
    if (blockIdx.x == 0 && threadIdx.x < Bb) out[threadIdx.x] = bout[0];
    if (blockIdx.x < TB) {
        __shared__ float tile[64][33];
        int tid = threadIdx.x;
        int tx = tid & 31, ty = tid >> 5;
        int nb = blockIdx.x * 32;
#pragma unroll
        for (int i = 0; i < 64; i += 8)
            tile[ty + i][tx] = x[(ty + i) * N0 + nb + tx];
        __syncthreads();
        int r = tid >> 3, q = tid & 7;
        __half2 h[4];
#pragma unroll
        for (int k = 0; k < 4; k++)
            h[k] = __floats2half2_rn(tile[q * 8 + 2 * k][r], tile[q * 8 + 2 * k + 1][r]);
        *(uint4*)&g_xT[(nb + r) * Bb + q * 8] = *(uint4*)h;
    } else {
        int i0 = ((blockIdx.x - TB) * 256 + threadIdx.x) * 4;
        if (i0 >= ETOT) return;
        const int* dp; int* cnt; int off;
        if (i0 < E0)            { dp = d0; cnt = g_cnt;            off = 0; }
        else if (i0 < E0 + E1)  { dp = d1; cnt = g_cnt + M0;       off = E0; }
        else                    { dp = d2; cnt = g_cnt + M0 + M1;  off = E0 + E1; }
        int4 dd = *(const int4*)&dp[i0 - off];
        int s0 = atomicAdd(&cnt[dd.x], 1);
        int s1 = atomicAdd(&cnt[dd.y], 1);
        int s2 = atomicAdd(&cnt[dd.z], 1);
        int s3 = atomicAdd(&cnt[dd.w], 1);
        *(int4*)&g_slot[i0] = make_int4(s0, s1, s2, s3);
    }
}

// ================= K2: exclusive scans (warp-shuffle, 8/thread); zero counters ======
__global__ void k_scan() {
    const int L = blockIdx.x;
    int* cnt    = (L == 0) ? g_cnt  : (L == 1) ? g_cnt + M0 : g_cnt + M0 + M1;
    int* rp     = (L == 0) ? g_rp0  : (L == 1) ? g_rp1      : g_rp2;
    const int m = (L == 0) ? M0     : (L == 1) ? M1         : M2;

    int t = threadIdx.x;
    int base = t * 8;
    int v[8];
    int s = 0;
#pragma unroll
    for (int k = 0; k < 8; k++) {
        int c = (base + k < m) ? cnt[base + k] : 0;
        s += c; v[k] = s;
    }
    int lane = t & 31, wid = t >> 5;
    int inc = s;
#pragma unroll
    for (int off = 1; off < 32; off <<= 1) {
        int n = __shfl_up_sync(0xffffffffu, inc, off);
        if (lane >= off) inc += n;
    }
    int wexcl = inc - s;
    __shared__ int wtot[32];
    if (lane == 31) wtot[wid] = inc;
    __syncthreads();
    if (t < 32) {
        int w = wtot[t];
        int wi = w;
#pragma unroll
        for (int off = 1; off < 32; off <<= 1) {
            int n = __shfl_up_sync(0xffffffffu, wi, off);
            if (t >= off) wi += n;
        }
        wtot[t] = wi - w;
    }
    __syncthreads();
    int off0 = wtot[wid] + wexcl;
#pragma unroll
    for (int k = 0; k < 8; k++)
        if (base + k < m) { rp[base + k + 1] = off0 + v[k]; cnt[base + k] = 0; }
    if (t == 0) rp[0] = 0;
}

// ================= K3: fill CSR via precomputed slots (no atomics) ==================
__global__ void k_fill(const int* __restrict__ s0, const int* __restrict__ d0,
                       const int* __restrict__ s1, const int* __restrict__ d1,
                       const int* __restrict__ s2, const int* __restrict__ d2) {
    int i0 = (blockIdx.x * 256 + threadIdx.x) * 4;
    if (i0 >= ETOT) return;
    const int *sp, *dp, *rp; int* ce; int off;
    if (i0 < E0)            { sp = s0; dp = d0; rp = g_rp0; ce = g_ce0; off = 0; }
    else if (i0 < E0 + E1)  { sp = s1; dp = d1; rp = g_rp1; ce = g_ce1; off = E0; }
    else                    { sp = s2; dp = d2; rp = g_rp2; ce = g_ce2; off = E0 + E1; }
    int j = i0 - off;
    int4 ss = *(const int4*)&sp[j];
    int4 dd = *(const int4*)&dp[j];
    int4 sl = *(const int4*)&g_slot[i0];
    ce[rp[dd.x] + sl.x] = ss.x;
    ce[rp[dd.y] + sl.y] = ss.y;
    ce[rp[dd.z] + sl.z] = ss.z;
    ce[rp[dd.w] + sl.w] = ss.w;
}

// ===== K4: layer 0 — warp per node, lane = 2 batches; scalar mean + minmax ==========
__global__ void k_agg0() {
    int lane = threadIdx.x & 31;
    int node = blockIdx.x * 8 + (threadIdx.x >> 5);
    int beg = g_rp0[node], end = g_rp0[node + 1];
    float ax = 0.f, ay = 0.f;
    for (int c = beg; c < end; c += 32) {
        int nchunk = min(32, end - c);
        int idx = (c + lane < end) ? g_ce0[c + lane] : 0;
        int k = 0;
#pragma unroll 2
        for (; k + 2 <= nchunk; k += 2) {
            int sA = __shfl_sync(0xffffffffu, idx, k);
            int sB = __shfl_sync(0xffffffffu, idx, k + 1);
            float2 fA = __half22float2(*(const __half2*)&g_xT[sA * Bb + 2 * lane]);
            float2 fB = __half22float2(*(const __half2*)&g_xT[sB * Bb + 2 * lane]);
            ax += fA.x + fB.x; ay += fA.y + fB.y;
        }
        if (k < nchunk) {
            int sA = __shfl_sync(0xffffffffu, idx, k);
            float2 fA = __half22float2(*(const __half2*)&g_xT[sA * Bb + 2 * lane]);
            ax += fA.x; ay += fA.y;
        }
    }
    float inv = 1.f / fmaxf((float)(end - beg), 1.f);
    float v0 = ax * inv, v1 = ay * inv;
    float mn = fminf(v0, v1), mx = fmaxf(v0, v1);
#pragma unroll
    for (int off = 16; off; off >>= 1) {
        mn = fminf(mn, __shfl_xor_sync(0xffffffffu, mn, off));
        mx = fmaxf(mx, __shfl_xor_sync(0xffffffffu, mx, off));
    }
    float ir = 1.f / (mx - mn + EPSV);
    float2 o = make_float2((v0 - mn) * ir, (v1 - mn) * ir);
    *(float2*)&g_u1[node * Bb + 2 * lane] = o;
}

// ===== K5: layer 1 — 128 thr/node (2 edge-chunks x 64 batches), 2 nodes/CTA =========
__global__ void k_agg1() {
    __shared__ float s_part[2][64];
    __shared__ float s_mn[2][2], s_mx[2][2];
    const int tid   = threadIdx.x;
    const int half  = tid >> 7;            // node within CTA: 0/1
    const int chunk = (tid >> 6) & 1;      // edge chunk: 0/1
    const int b     = tid & 63;
    const int lane  = tid & 31;
    const int node  = blockIdx.x * 2 + half;
    int beg = g_rp1[node], end = g_rp1[node + 1];
    float a = 0.f;
    int j = beg + chunk;
    for (; j + 6 < end; j += 8) {          // 4 independent scalar loads / iter
        int i0 = g_ce1[j],     i1 = g_ce1[j + 2];
        int i2 = g_ce1[j + 4], i3 = g_ce1[j + 6];
        float f0 = g_u1[i0 * Bb + b], f1 = g_u1[i1 * Bb + b];
        float f2 = g_u1[i2 * Bb + b], f3 = g_u1[i3 * Bb + b];
        a += (f0 + f1) + (f2 + f3);
    }
    for (; j < end; j += 2) a += g_u1[g_ce1[j] * Bb + b];
    if (chunk == 1) s_part[half][b] = a;
    __syncthreads();
    float t = 0.f;
    if (chunk == 0) {
        a += s_part[half][b];
        t = a / fmaxf((float)(end - beg), 1.f);
        float mn = t, mx = t;
#pragma unroll
        for (int off = 16; off; off >>= 1) {
            mn = fminf(mn, __shfl_xor_sync(0xffffffffu, mn, off));
            mx = fmaxf(mx, __shfl_xor_sync(0xffffffffu, mx, off));
        }
        if (lane == 0) {
            int wig = (tid >> 5) & 1;
            s_mn[half][wig] = mn; s_mx[half][wig] = mx;
        }
    }
    __syncthreads();                       // CTA-uniform
    if (chunk == 0) {
        float mn = fminf(s_mn[half][0], s_mn[half][1]);
        float mx = fmaxf(s_mx[half][0], s_mx[half][1]);
        g_u2[node * Bb + b] = (t - mn) / (mx - mn + EPSV);
    }
}

// ===== K6: layer 2 + output — 128 thr/node, 2 nodes/CTA; sign-folded Wout dot =======
__global__ void k_agg2out(const float* __restrict__ W0, const float* __restrict__ W1,
                          const float* __restrict__ W2, const float* __restrict__ Wout,
                          float* __restrict__ out) {
    __shared__ float s_part[2][64];
    __shared__ float s_mn[2][2], s_mx[2][2];
    const int tid   = threadIdx.x;
    const int half  = tid >> 7;
    const int chunk = (tid >> 6) & 1;
    const int b     = tid & 63;
    const int lane  = tid & 31;
    const int node  = blockIdx.x * 2 + half;
    int beg = g_rp2[node], end = g_rp2[node + 1];
    float a = 0.f;
    int j = beg + chunk;
    for (; j + 6 < end; j += 8) {
        int i0 = g_ce2[j],     i1 = g_ce2[j + 2];
        int i2 = g_ce2[j + 4], i3 = g_ce2[j + 6];
        float f0 = g_u2[i0 * Bb + b], f1 = g_u2[i1 * Bb + b];
        float f2 = g_u2[i2 * Bb + b], f3 = g_u2[i3 * Bb + b];
        a += (f0 + f1) + (f2 + f3);
    }
    for (; j < end; j += 2) a += g_u2[g_ce2[j] * Bb + b];
    if (chunk == 1) s_part[half][b] = a;
    __syncthreads();
    float t = 0.f;
    if (chunk == 0) {
        a += s_part[half][b];
        t = a / fmaxf((float)(end - beg), 1.f);
        float mn = t, mx = t;
#pragma unroll
        for (int off = 16; off; off >>= 1) {
            mn = fminf(mn, __shfl_xor_sync(0xffffffffu, mn, off));
            mx = fmaxf(mx, __shfl_xor_sync(0xffffffffu, mx, off));
        }
        if (lane == 0) {
            int wig = (tid >> 5) & 1;
            s_mn[half][wig] = mn; s_mx[half][wig] = mx;
        }
    }
    __syncthreads();                       // CTA-uniform
    if (chunk == 0) {
        float mn = fminf(s_mn[half][0], s_mn[half][1]);
        float mx = fmaxf(s_mx[half][0], s_mx[half][1]);
        float u3 = (t - mn) / (mx - mn + EPSV);
        // global sign patterns from W0 -> W1 -> W2 (tiny, uniform across threads)
        float a1[8];
#pragma unroll
        for (int d = 0; d < 8; d++) {
            float w = W0[d];
            a1[d] = (w > 0.f) ? 1.f : ((w < 0.f) ? -1.f : 0.f);
        }
        float a2[8];
#pragma unroll
        for (int h = 0; h < 8; h++) {
            float al = 0.f;
#pragma unroll
            for (int d = 0; d < 8; d++) al += W1[h * 8 + d] * a1[d];
            a2[h] = (al > 0.f) ? 1.f : ((al < 0.f) ? -1.f : 0.f);
        }
        float wq = 0.f, cp = 0.f;
#pragma unroll
        for (int h = 0; h < 8; h++) {
            float al = 0.f;
#pragma unroll
            for (int d = 0; d < 8; d++) al += W2[h * 8 + d] * a2[d];
            float wo = Wout[node * 8 + h];
            if (al > 0.f)      { wq += wo; }
            else if (al < 0.f) { wq -= wo; cp += wo; }
        }
        atomicAdd(&out[b], u3 * wq + cp);
    }
}

extern "C" void kernel_launch(void* const* d_in, const int* in_sizes, int n_in,
                              void* d_out, int out_size) {
    const float* x    = (const float*)d_in[0];
    const int*   e0s  = (const int*)d_in[1];
    const int*   e0d  = (const int*)d_in[2];
    const int*   e1s  = (const int*)d_in[3];
    const int*   e1d  = (const int*)d_in[4];
    const int*   e2s  = (const int*)d_in[5];
    const int*   e2d  = (const int*)d_in[6];
    const float* W0   = (const float*)d_in[7];
    const float* W1   = (const float*)d_in[8];
    const float* W2   = (const float*)d_in[9];
    const float* Wout = (const float*)d_in[10];
    const float* bout = (const float*)d_in[11];
    float* out = (float*)d_out;

    k_pre<<<TB + EB, 256>>>(x, e0d, e1d, e2d, bout, out);
    k_scan<<<3, 1024>>>();
    k_fill<<<EB, 256>>>(e0s, e0d, e1s, e1d, e2s, e2d);
    k_agg0<<<M0 / 8, 256>>>();
    k_agg1<<<M1 / 2, 256>>>();
    k_agg2out<<<M2 / 2, 256>>>(W0, W1, W2, Wout, out);
}

// round 17
// speedup vs baseline: 1.5052x; 1.0246x over previous
#include <cuda_runtime.h>
#include <cuda_fp16.h>

#define EPSV 1e-8f

constexpr int Bb = 64;
constexpr int N0 = 20000, E0 = 200000, M0 = 8000;
constexpr int E1 = 80000,  M1 = 2000;
constexpr int E2 = 20000,  M2 = 500;
constexpr int ETOT = E0 + E1 + E2;
constexpr int MTOT = M0 + M1 + M2;

constexpr int TB = N0 / 32;                    // 625 transpose blocks
constexpr int EB = (ETOT / 4 + 255) / 256;     // 293 edge blocks (hist, 4 edges/thread)
constexpr int FB = (ETOT / 8 + 255) / 256;     // 147 fill blocks (8 edges/thread)

// ---- scratch (device globals; zero-initialized at module load) ----
__device__ __half g_xT[N0 * Bb];               // x transposed (node, batch) fp16
__device__ int    g_cnt[MTOT];                 // degree counters (re-zeroed by k_scan)
__device__ int    g_slot[ETOT];                // per-edge slot in its dst bucket
__device__ int    g_rp0[M0 + 1], g_rp1[M1 + 1], g_rp2[M2 + 1];
__device__ int    g_ce0[E0], g_ce1[E1], g_ce2[E2];
__device__ float  g_u1[M0 * Bb];               // layer-0 scalar minmax output, fp32
__device__ float  g_u2[M1 * Bb];               // layer-1 scalar minmax output, fp32

// ================= K1: transpose (tiles) || histogram+slots || out init =============
__global__ void k_pre(const float* __restrict__ x,
                      const int* __restrict__ d0, const int* __restrict__ d1,
                      const int* __restrict__ d2,
                      const float* __restrict__ bout, float* __restrict__ out) {
    if (blockIdx.x == 0 && threadIdx.x < Bb) out[threadIdx.x] = bout[0];
    if (blockIdx.x < TB) {
        __shared__ float tile[64][33];
        int tid = threadIdx.x;
        int tx = tid & 31, ty = tid >> 5;
        int nb = blockIdx.x * 32;
#pragma unroll
        for (int i = 0; i < 64; i += 8)
            tile[ty + i][tx] = x[(ty + i) * N0 + nb + tx];
        __syncthreads();
        int r = tid >> 3, q = tid & 7;
        __half2 h[4];
#pragma unroll
        for (int k = 0; k < 4; k++)
            h[k] = __floats2half2_rn(tile[q * 8 + 2 * k][r], tile[q * 8 + 2 * k + 1][r]);
        *(uint4*)&g_xT[(nb + r) * Bb + q * 8] = *(uint4*)h;
    } else {
        int i0 = ((blockIdx.x - TB) * 256 + threadIdx.x) * 4;
        if (i0 >= ETOT) return;
        const int* dp; int* cnt; int off;
        if (i0 < E0)            { dp = d0; cnt = g_cnt;            off = 0; }
        else if (i0 < E0 + E1)  { dp = d1; cnt = g_cnt + M0;       off = E0; }
        else                    { dp = d2; cnt = g_cnt + M0 + M1;  off = E0 + E1; }
        int4 dd = *(const int4*)&dp[i0 - off];
        int s0 = atomicAdd(&cnt[dd.x], 1);
        int s1 = atomicAdd(&cnt[dd.y], 1);
        int s2 = atomicAdd(&cnt[dd.z], 1);
        int s3 = atomicAdd(&cnt[dd.w], 1);
        *(int4*)&g_slot[i0] = make_int4(s0, s1, s2, s3);
    }
}

// ================= K2: exclusive scans (warp-shuffle, 8/thread); zero counters ======
__global__ void k_scan() {
    const int L = blockIdx.x;
    int* cnt    = (L == 0) ? g_cnt  : (L == 1) ? g_cnt + M0 : g_cnt + M0 + M1;
    int* rp     = (L == 0) ? g_rp0  : (L == 1) ? g_rp1      : g_rp2;
    const int m = (L == 0) ? M0     : (L == 1) ? M1         : M2;

    int t = threadIdx.x;
    int base = t * 8;
    int v[8];
    int s = 0;
#pragma unroll
    for (int k = 0; k < 8; k++) {
        int c = (base + k < m) ? cnt[base + k] : 0;
        s += c; v[k] = s;
    }
    int lane = t & 31, wid = t >> 5;
    int inc = s;
#pragma unroll
    for (int off = 1; off < 32; off <<= 1) {
        int n = __shfl_up_sync(0xffffffffu, inc, off);
        if (lane >= off) inc += n;
    }
    int wexcl = inc - s;
    __shared__ int wtot[32];
    if (lane == 31) wtot[wid] = inc;
    __syncthreads();
    if (t < 32) {
        int w = wtot[t];
        int wi = w;
#pragma unroll
        for (int off = 1; off < 32; off <<= 1) {
            int n = __shfl_up_sync(0xffffffffu, wi, off);
            if (t >= off) wi += n;
        }
        wtot[t] = wi - w;
    }
    __syncthreads();
    int off0 = wtot[wid] + wexcl;
#pragma unroll
    for (int k = 0; k < 8; k++)
        if (base + k < m) { rp[base + k + 1] = off0 + v[k]; cnt[base + k] = 0; }
    if (t == 0) rp[0] = 0;
}

// ============ K3: fill CSR via precomputed slots (no atomics), 8 edges/thread =======
__global__ void k_fill(const int* __restrict__ s0, const int* __restrict__ d0,
                       const int* __restrict__ s1, const int* __restrict__ d1,
                       const int* __restrict__ s2, const int* __restrict__ d2) {
    int i0 = (blockIdx.x * 256 + threadIdx.x) * 8;
    if (i0 >= ETOT) return;
    const int *sp, *dp, *rp; int* ce; int off;
    if (i0 < E0)            { sp = s0; dp = d0; rp = g_rp0; ce = g_ce0; off = 0; }
    else if (i0 < E0 + E1)  { sp = s1; dp = d1; rp = g_rp1; ce = g_ce1; off = E0; }
    else                    { sp = s2; dp = d2; rp = g_rp2; ce = g_ce2; off = E0 + E1; }
    int j = i0 - off;
    int4 sa = *(const int4*)&sp[j],     sb = *(const int4*)&sp[j + 4];
    int4 da = *(const int4*)&dp[j],     db = *(const int4*)&dp[j + 4];
    int4 la = *(const int4*)&g_slot[i0], lb = *(const int4*)&g_slot[i0 + 4];
    ce[rp[da.x] + la.x] = sa.x;
    ce[rp[da.y] + la.y] = sa.y;
    ce[rp[da.z] + la.z] = sa.z;
    ce[rp[da.w] + la.w] = sa.w;
    ce[rp[db.x] + lb.x] = sb.x;
    ce[rp[db.y] + lb.y] = sb.y;
    ce[rp[db.z] + lb.z] = sb.z;
    ce[rp[db.w] + lb.w] = sb.w;
}

// ===== K4: layer 0 — warp per node; lane = (edge-quad el, batch-octet oct) ==========
__global__ void k_agg0() {
    const int lane = threadIdx.x & 31;
    const int el   = lane >> 3;            // edge slot within quad: 0..3
    const int oct  = lane & 7;             // batch octet: 0..7
    const int node = blockIdx.x * 8 + (threadIdx.x >> 5);
    int beg = g_rp0[node], end = g_rp0[node + 1];
    float acc[8];
#pragma unroll
    for (int j = 0; j < 8; j++) acc[j] = 0.f;
    for (int c = beg; c < end; c += 32) {
        int nchunk = min(32, end - c);
        int idx = (c + lane < end) ? g_ce0[c + lane] : 0;
        int nr = nchunk >> 2;
#pragma unroll 2
        for (int r = 0; r < nr; r++) {
            int src = __shfl_sync(0xffffffffu, idx, r * 4 + el);
            uint4 v = *(const uint4*)&g_xT[src * Bb + oct * 8];
            float2 f;
            f = __half22float2(*(__half2*)&v.x); acc[0] += f.x; acc[1] += f.y;
            f = __half22float2(*(__half2*)&v.y); acc[2] += f.x; acc[3] += f.y;
            f = __half22float2(*(__half2*)&v.z); acc[4] += f.x; acc[5] += f.y;
            f = __half22float2(*(__half2*)&v.w); acc[6] += f.x; acc[7] += f.y;
        }
        int rem = nchunk & 3;
        if (rem) {
            int src = __shfl_sync(0xffffffffu, idx, nr * 4 + min(el, rem - 1));
            if (el < rem) {
                uint4 v = *(const uint4*)&g_xT[src * Bb + oct * 8];
                float2 f;
                f = __half22float2(*(__half2*)&v.x); acc[0] += f.x; acc[1] += f.y;
                f = __half22float2(*(__half2*)&v.y); acc[2] += f.x; acc[3] += f.y;
                f = __half22float2(*(__half2*)&v.z); acc[4] += f.x; acc[5] += f.y;
                f = __half22float2(*(__half2*)&v.w); acc[6] += f.x; acc[7] += f.y;
            }
        }
    }
    // reduce across the 4 edge-slots (lane bits 3,4)
#pragma unroll
    for (int off = 8; off <= 16; off <<= 1) {
#pragma unroll
        for (int j = 0; j < 8; j++)
            acc[j] += __shfl_xor_sync(0xffffffffu, acc[j], off);
    }
    float inv = 1.f / fmaxf((float)(end - beg), 1.f);
    float s[8];
#pragma unroll
    for (int j = 0; j < 8; j++) s[j] = acc[j] * inv;
    float mn = s[0], mx = s[0];
#pragma unroll
    for (int j = 1; j < 8; j++) { mn = fminf(mn, s[j]); mx = fmaxf(mx, s[j]); }
#pragma unroll
    for (int off = 1; off <= 4; off <<= 1) {
        mn = fminf(mn, __shfl_xor_sync(0xffffffffu, mn, off));
        mx = fmaxf(mx, __shfl_xor_sync(0xffffffffu, mx, off));
    }
    float ir = 1.f / (mx - mn + EPSV);
    // each lane writes 2 batches: oct*8 + el*2 (+1)
    int bA = oct * 8 + el * 2;
    float2 o = make_float2((s[el * 2] - mn) * ir, (s[el * 2 + 1] - mn) * ir);
    *(float2*)&g_u1[node * Bb + bA] = o;
}

// ===== K5: layer 1 — 128 thr/node (2 edge-chunks x 64 batches), 2 nodes/CTA =========
__global__ void k_agg1() {
    __shared__ float s_part[2][64];
    __shared__ float s_mn[2][2], s_mx[2][2];
    const int tid   = threadIdx.x;
    const int half  = tid >> 7;            // node within CTA: 0/1
    const int chunk = (tid >> 6) & 1;      // edge chunk: 0/1
    const int b     = tid & 63;
    const int lane  = tid & 31;
    const int node  = blockIdx.x * 2 + half;
    int beg = g_rp1[node], end = g_rp1[node + 1];
    float a = 0.f;
    int j = beg + chunk;
    for (; j + 14 < end; j += 16) {        // 8 independent scalar loads / iter
        int i0 = g_ce1[j],      i1 = g_ce1[j + 2];
        int i2 = g_ce1[j + 4],  i3 = g_ce1[j + 6];
        int i4 = g_ce1[j + 8],  i5 = g_ce1[j + 10];
        int i6 = g_ce1[j + 12], i7 = g_ce1[j + 14];
        float f0 = g_u1[i0 * Bb + b], f1 = g_u1[i1 * Bb + b];
        float f2 = g_u1[i2 * Bb + b], f3 = g_u1[i3 * Bb + b];
        float f4 = g_u1[i4 * Bb + b], f5 = g_u1[i5 * Bb + b];
        float f6 = g_u1[i6 * Bb + b], f7 = g_u1[i7 * Bb + b];
        a += ((f0 + f1) + (f2 + f3)) + ((f4 + f5) + (f6 + f7));
    }
    for (; j < end; j += 2) a += g_u1[g_ce1[j] * Bb + b];
    if (chunk == 1) s_part[half][b] = a;
    __syncthreads();
    float t = 0.f;
    if (chunk == 0) {
        a += s_part[half][b];
        t = a / fmaxf((float)(end - beg), 1.f);
        float mn = t, mx = t;
#pragma unroll
        for (int off = 16; off; off >>= 1) {
            mn = fminf(mn, __shfl_xor_sync(0xffffffffu, mn, off));
            mx = fmaxf(mx, __shfl_xor_sync(0xffffffffu, mx, off));
        }
        if (lane == 0) {
            int wig = (tid >> 5) & 1;
            s_mn[half][wig] = mn; s_mx[half][wig] = mx;
        }
    }
    __syncthreads();                       // CTA-uniform
    if (chunk == 0) {
        float mn = fminf(s_mn[half][0], s_mn[half][1]);
        float mx = fmaxf(s_mx[half][0], s_mx[half][1]);
        g_u2[node * Bb + b] = (t - mn) / (mx - mn + EPSV);
    }
}

// ===== K6: layer 2 + output — 128 thr/node, 2 nodes/CTA; sign-folded Wout dot =======
__global__ void k_agg2out(const float* __restrict__ W0, const float* __restrict__ W1,
                          const float* __restrict__ W2, const float* __restrict__ Wout,
                          float* __restrict__ out) {
    __shared__ float s_part[2][64];
    __shared__ float s_mn[2][2], s_mx[2][2];
    const int tid   = threadIdx.x;
    const int half  = tid >> 7;
    const int chunk = (tid >> 6) & 1;
    const int b     = tid & 63;
    const int lane  = tid & 31;
    const int node  = blockIdx.x * 2 + half;
    int beg = g_rp2[node], end = g_rp2[node + 1];
    float a = 0.f;
    int j = beg + chunk;
    for (; j + 6 < end; j += 8) {
        int i0 = g_ce2[j],     i1 = g_ce2[j + 2];
        int i2 = g_ce2[j + 4], i3 = g_ce2[j + 6];
        float f0 = g_u2[i0 * Bb + b], f1 = g_u2[i1 * Bb + b];
        float f2 = g_u2[i2 * Bb + b], f3 = g_u2[i3 * Bb + b];
        a += (f0 + f1) + (f2 + f3);
    }
    for (; j < end; j += 2) a += g_u2[g_ce2[j] * Bb + b];
    if (chunk == 1) s_part[half][b] = a;
    __syncthreads();
    float t = 0.f;
    if (chunk == 0) {
        a += s_part[half][b];
        t = a / fmaxf((float)(end - beg), 1.f);
        float mn = t, mx = t;
#pragma unroll
        for (int off = 16; off; off >>= 1) {
            mn = fminf(mn, __shfl_xor_sync(0xffffffffu, mn, off));
            mx = fmaxf(mx, __shfl_xor_sync(0xffffffffu, mx, off));
        }
        if (lane == 0) {
            int wig = (tid >> 5) & 1;
            s_mn[half][wig] = mn; s_mx[half][wig] = mx;
        }
    }
    __syncthreads();                       // CTA-uniform
    if (chunk == 0) {
        float mn = fminf(s_mn[half][0], s_mn[half][1]);
        float mx = fmaxf(s_mx[half][0], s_mx[half][1]);
        float u3 = (t - mn) / (mx - mn + EPSV);
        // global sign patterns from W0 -> W1 -> W2 (tiny, uniform across threads)
        float a1[8];
#pragma unroll
        for (int d = 0; d < 8; d++) {
            float w = W0[d];
            a1[d] = (w > 0.f) ? 1.f : ((w < 0.f) ? -1.f : 0.f);
        }
        float a2[8];
#pragma unroll
        for (int h = 0; h < 8; h++) {
            float al = 0.f;
#pragma unroll
            for (int d = 0; d < 8; d++) al += W1[h * 8 + d] * a1[d];
            a2[h] = (al > 0.f) ? 1.f : ((al < 0.f) ? -1.f : 0.f);
        }
        float wq = 0.f, cp = 0.f;
#pragma unroll
        for (int h = 0; h < 8; h++) {
            float al = 0.f;
#pragma unroll
            for (int d = 0; d < 8; d++) al += W2[h * 8 + d] * a2[d];
            float wo = Wout[node * 8 + h];
            if (al > 0.f)      { wq += wo; }
            else if (al < 0.f) { wq -= wo; cp += wo; }
        }
        atomicAdd(&out[b], u3 * wq + cp);
    }
}

extern "C" void kernel_launch(void* const* d_in, const int* in_sizes, int n_in,
                              void* d_out, int out_size) {
    const float* x    = (const float*)d_in[0];
    const int*   e0s  = (const int*)d_in[1];
    const int*   e0d  = (const int*)d_in[2];
    const int*   e1s  = (const int*)d_in[3];
    const int*   e1d  = (const int*)d_in[4];
    const int*   e2s  = (const int*)d_in[5];
    const int*   e2d  = (const int*)d_in[6];
    const float* W0   = (const float*)d_in[7];
    const float* W1   = (const float*)d_in[8];
    const float* W2   = (const float*)d_in[9];
    const float* Wout = (const float*)d_in[10];
    const float* bout = (const float*)d_in[11];
    float* out = (float*)d_out;

    k_pre<<<TB + EB, 256>>>(x, e0d, e1d, e2d, bout, out);
    k_scan<<<3, 1024>>>();
    k_fill<<<FB, 256>>>(e0s, e0d, e1s, e1d, e2s, e2d);
    k_agg0<<<M0 / 8, 256>>>();
    k_agg1<<<M1 / 2, 256>>>();
    k_agg2out<<<M2 / 2, 256>>>(W0, W1, W2, Wout, out);
}